// round 3
// baseline (speedup 1.0000x reference)
#include <cuda_runtime.h>
#include <cuda_fp16.h>
#include <cstdint>
#include <cstddef>

// out[b,o] = sum_{l,c} x[b,l,c]*W_pos[o,l]*W_chan[o,c]
//  == GEMM: A[m=b, k=l*32+c] (= x, already K-contiguous) @ B[n=o, k]^T
//  with B = W2[o, l*32+c] = W_pos[o,l]*W_chan[o,c], materialized in fp16.
// Consumer: mma.sync.m16n8k16 (f16 -> f32 accum), ldmatrix, cp.async pipeline.
// (tcgen05 unavailable: harness PTX target is sm_103 without the 'a' suffix.)

static constexpr int MB = 1024, NO = 2048, LL = 2048, CC = 32;
static constexpr int KK = LL * CC;                  // 65536

__device__ __half g_xh[(size_t)MB * KK];            // 128 MiB fp16 A
__device__ __half g_w2[(size_t)NO * KK];            // 256 MiB fp16 B

__device__ __forceinline__ uint32_t pk(float a, float b) {
    __half2 h = __floats2half2_rn(a, b);
    return *reinterpret_cast<uint32_t*>(&h);
}

__global__ void k_convert(const float4* __restrict__ x4) {
    int i = blockIdx.x * 256 + threadIdx.x;
    float4 v = x4[i];
    uint2 u; u.x = pk(v.x, v.y); u.y = pk(v.z, v.w);
    reinterpret_cast<uint2*>(g_xh)[i] = u;
}

__global__ void k_w2(const float* __restrict__ Wp, const float* __restrict__ Wc) {
    int o = blockIdx.x;
    __shared__ float wc[CC];
    if (threadIdx.x < CC) wc[threadIdx.x] = Wc[o * CC + threadIdx.x];
    __syncthreads();
    for (int l = threadIdx.x; l < LL; l += blockDim.x) {
        float wp = Wp[o * LL + l];
        uint4* dst = reinterpret_cast<uint4*>(g_w2 + (size_t)o * KK + (size_t)l * CC);
#pragma unroll
        for (int q = 0; q < 4; ++q) {
            uint4 u;
            u.x = pk(wp * wc[8*q+0], wp * wc[8*q+1]);
            u.y = pk(wp * wc[8*q+2], wp * wc[8*q+3]);
            u.z = pk(wp * wc[8*q+4], wp * wc[8*q+5]);
            u.w = pk(wp * wc[8*q+6], wp * wc[8*q+7]);
            dst[q] = u;
        }
    }
}

// ---------------- helpers ----------------
__device__ __forceinline__ uint32_t smem_u32(const void* p) {
    uint32_t a;
    asm("{ .reg .u64 t; cvta.to.shared.u64 t, %1; cvt.u32.u64 %0, t; }" : "=r"(a) : "l"(p));
    return a;
}
__device__ __forceinline__ void cpa16(uint32_t s, const void* g) {
    asm volatile("cp.async.cg.shared.global [%0], [%1], 16;" :: "r"(s), "l"(g) : "memory");
}
#define CP_COMMIT() asm volatile("cp.async.commit_group;" ::: "memory")
#define CP_WAIT(n)  asm volatile("cp.async.wait_group %0;" :: "n"(n) : "memory")

__device__ __forceinline__ void ldsm4(uint32_t* r, uint32_t a) {
    asm volatile("ldmatrix.sync.aligned.m8n8.x4.shared.b16 {%0,%1,%2,%3}, [%4];"
                 : "=r"(r[0]), "=r"(r[1]), "=r"(r[2]), "=r"(r[3]) : "r"(a));
}
__device__ __forceinline__ void mma16816(float* c, const uint32_t* a,
                                         uint32_t b0, uint32_t b1) {
    asm volatile("mma.sync.aligned.m16n8k16.row.col.f32.f16.f16.f32 "
                 "{%0,%1,%2,%3}, {%4,%5,%6,%7}, {%8,%9}, {%0,%1,%2,%3};"
                 : "+f"(c[0]), "+f"(c[1]), "+f"(c[2]), "+f"(c[3])
                 : "r"(a[0]), "r"(a[1]), "r"(a[2]), "r"(a[3]), "r"(b0), "r"(b1));
}

// ---------------- GEMM: CTA 128x128, warp 64x64 (2x2 warps), KT=64, 4-stage ----------------
static constexpr int BM = 128, BN = 128, KT = 64;
static constexpr int NIT = KK / KT;                 // 1024
static constexpr int STG = 4;
static constexpr uint32_t ATILE = BM * KT * 2;      // 16384
static constexpr uint32_t STAGE_BYTES = 2 * ATILE;  // 32768 (A + B)
static constexpr uint32_t SMEM_BYTES = STG * STAGE_BYTES;   // 131072

__global__ void __launch_bounds__(128, 1) k_gemm(float* __restrict__ out) {
    extern __shared__ char smem[];
    const uint32_t sb = smem_u32(smem);
    const int t = threadIdx.x;
    const int w = t >> 5, l = t & 31;
    const int m0 = blockIdx.y * BM, n0 = blockIdx.x * BN;
    const int wm = (w >> 1) * 64, wn = (w & 1) * 64;

    // loader: thread t owns row t of both tiles (8 x 16B chunks, SW128 swizzle)
    const __half* gA = g_xh + (size_t)(m0 + t) * KK;
    const __half* gB = g_w2 + (size_t)(n0 + t) * KK;
    const uint32_t rswz = (uint32_t)(t & 7);

    float acc[4][8][4];
#pragma unroll
    for (int i = 0; i < 4; ++i)
#pragma unroll
        for (int j = 0; j < 8; ++j)
#pragma unroll
            for (int k = 0; k < 4; ++k) acc[i][j][k] = 0.f;

    auto load_stage = [&](int it) {
        const uint32_t st = sb + (uint32_t)(it & (STG - 1)) * STAGE_BYTES;
        const __half* ga = gA + (size_t)it * KT;
        const __half* gb = gB + (size_t)it * KT;
        const uint32_t rowA = st + (uint32_t)t * 128u;
        const uint32_t rowB = rowA + ATILE;
#pragma unroll
        for (int i = 0; i < 8; ++i) {
            const uint32_t so = ((uint32_t)i ^ rswz) * 16u;
            cpa16(rowA + so, ga + i * 8);
            cpa16(rowB + so, gb + i * 8);
        }
    };

    // prologue: stages 0..STG-2
#pragma unroll
    for (int s = 0; s < STG - 1; ++s) { load_stage(s); CP_COMMIT(); }

    // precomputed ldmatrix lane geometry
    const int arow_i = (l & 7) + ((l >> 3) & 1) * 8;        // within 16-row group (A)
    const int achk_i = (l >> 4);                            // 16B chunk (A)
    const int brow_i = (l & 7) + ((l >> 4) << 3);           // within 16-row group (B)
    const int bchk_i = (l >> 3) & 1;                        // 16B chunk (B)

    for (int it = 0; it < NIT; ++it) {
        CP_WAIT(STG - 2);
        __syncthreads();
        if (it + STG - 1 < NIT) load_stage(it + STG - 1);
        CP_COMMIT();

        const uint32_t st = sb + (uint32_t)(it & (STG - 1)) * STAGE_BYTES;
#pragma unroll
        for (int ks = 0; ks < KT / 16; ++ks) {
            uint32_t a[4][4], b[4][4];
#pragma unroll
            for (int mi = 0; mi < 4; ++mi) {
                const int row = wm + mi * 16 + arow_i;
                const int chk = achk_i + ks * 2;
                ldsm4(a[mi], st + (uint32_t)(row * 128 + ((chk ^ (row & 7)) * 16)));
            }
#pragma unroll
            for (int nj = 0; nj < 4; ++nj) {
                const int row = wn + nj * 16 + brow_i;
                const int chk = bchk_i + ks * 2;
                ldsm4(b[nj], st + ATILE + (uint32_t)(row * 128 + ((chk ^ (row & 7)) * 16)));
            }
#pragma unroll
            for (int mi = 0; mi < 4; ++mi)
#pragma unroll
                for (int nj = 0; nj < 8; ++nj)
                    mma16816(acc[mi][nj], a[mi],
                             b[nj >> 1][(nj & 1) * 2], b[nj >> 1][(nj & 1) * 2 + 1]);
        }
    }

    // epilogue: c layout m16n8: rows (l>>2), (l>>2)+8; cols (l&3)*2 (+1)
#pragma unroll
    for (int mi = 0; mi < 4; ++mi) {
        const int row = m0 + wm + mi * 16 + (l >> 2);
#pragma unroll
        for (int nj = 0; nj < 8; ++nj) {
            const int col = n0 + wn + nj * 8 + (l & 3) * 2;
            float2 lo; lo.x = acc[mi][nj][0]; lo.y = acc[mi][nj][1];
            float2 hi; hi.x = acc[mi][nj][2]; hi.y = acc[mi][nj][3];
            *reinterpret_cast<float2*>(out + (size_t)row * NO + col) = lo;
            *reinterpret_cast<float2*>(out + (size_t)(row + 8) * NO + col) = hi;
        }
    }
}

extern "C" void kernel_launch(void* const* d_in, const int* in_sizes, int n_in,
                              void* d_out, int out_size) {
    (void)in_sizes; (void)n_in; (void)out_size;
    const float* x  = (const float*)d_in[0];
    const float* Wp = (const float*)d_in[1];
    const float* Wc = (const float*)d_in[2];
    float* out = (float*)d_out;

    k_convert<<<(MB * (KK / 4)) / 256, 256>>>(reinterpret_cast<const float4*>(x));
    k_w2<<<NO, 256>>>(Wp, Wc);
    cudaFuncSetAttribute(k_gemm, cudaFuncAttributeMaxDynamicSharedMemorySize,
                         (int)SMEM_BYTES);
    dim3 grid(NO / BN, MB / BM);
    k_gemm<<<grid, 128, SMEM_BYTES>>>(out);
}

// round 4
// speedup vs baseline: 1.3861x; 1.3861x over previous
#include <cuda_runtime.h>
#include <cuda_fp16.h>
#include <cstdint>
#include <cstddef>

// out = x[1024,65536] @ W2[2048,65536]^T, W2[o,l*32+c]=W_pos[o,l]*W_chan[o,c],
// fp16 operands / fp32 accum via mma.sync.m16n8k16 (tcgen05 unavailable: PTX
// target is plain sm_103). CTA 128x128x64, 8 warps (warp 64x32), 4-stage cp.async.

static constexpr int MB = 1024, NO = 2048, LL = 2048, CC = 32;
static constexpr int KK = LL * CC;                  // 65536

__device__ __half g_xh[(size_t)MB * KK];
__device__ __half g_w2[(size_t)NO * KK];

__device__ __forceinline__ uint32_t pk(float a, float b) {
    __half2 h = __floats2half2_rn(a, b);
    return *reinterpret_cast<uint32_t*>(&h);
}

__global__ void k_convert(const float4* __restrict__ x4) {
    int i = blockIdx.x * 256 + threadIdx.x;
    float4 v = x4[i];
    uint2 u; u.x = pk(v.x, v.y); u.y = pk(v.z, v.w);
    reinterpret_cast<uint2*>(g_xh)[i] = u;
}

__global__ void k_w2(const float* __restrict__ Wp, const float* __restrict__ Wc) {
    int o = blockIdx.x;
    __shared__ float wc[CC];
    if (threadIdx.x < CC) wc[threadIdx.x] = Wc[o * CC + threadIdx.x];
    __syncthreads();
    for (int l = threadIdx.x; l < LL; l += blockDim.x) {
        float wp = Wp[o * LL + l];
        uint4* dst = reinterpret_cast<uint4*>(g_w2 + (size_t)o * KK + (size_t)l * CC);
#pragma unroll
        for (int q = 0; q < 4; ++q) {
            uint4 u;
            u.x = pk(wp * wc[8*q+0], wp * wc[8*q+1]);
            u.y = pk(wp * wc[8*q+2], wp * wc[8*q+3]);
            u.z = pk(wp * wc[8*q+4], wp * wc[8*q+5]);
            u.w = pk(wp * wc[8*q+6], wp * wc[8*q+7]);
            dst[q] = u;
        }
    }
}

__device__ __forceinline__ uint32_t smem_u32(const void* p) {
    uint32_t a;
    asm("{ .reg .u64 t; cvta.to.shared.u64 t, %1; cvt.u32.u64 %0, t; }" : "=r"(a) : "l"(p));
    return a;
}
__device__ __forceinline__ void cpa16(uint32_t s, const void* g) {
    asm volatile("cp.async.cg.shared.global [%0], [%1], 16;" :: "r"(s), "l"(g) : "memory");
}
#define CP_COMMIT() asm volatile("cp.async.commit_group;" ::: "memory")
#define CP_WAIT(n)  asm volatile("cp.async.wait_group %0;" :: "n"(n) : "memory")

__device__ __forceinline__ void ldsm4(uint32_t* r, uint32_t a) {
    asm volatile("ldmatrix.sync.aligned.m8n8.x4.shared.b16 {%0,%1,%2,%3}, [%4];"
                 : "=r"(r[0]), "=r"(r[1]), "=r"(r[2]), "=r"(r[3]) : "r"(a));
}
__device__ __forceinline__ void mma16816(float* c, const uint32_t* a,
                                         uint32_t b0, uint32_t b1) {
    asm volatile("mma.sync.aligned.m16n8k16.row.col.f32.f16.f16.f32 "
                 "{%0,%1,%2,%3}, {%4,%5,%6,%7}, {%8,%9}, {%0,%1,%2,%3};"
                 : "+f"(c[0]), "+f"(c[1]), "+f"(c[2]), "+f"(c[3])
                 : "r"(a[0]), "r"(a[1]), "r"(a[2]), "r"(a[3]), "r"(b0), "r"(b1));
}

static constexpr int BM = 128, BN = 128, KT = 64;
static constexpr int NIT = KK / KT;                 // 1024
static constexpr int STG = 4;
static constexpr uint32_t ATILE = BM * KT * 2;      // 16384
static constexpr uint32_t STAGE_BYTES = 2 * ATILE;  // 32768
static constexpr uint32_t SMEM_BYTES = STG * STAGE_BYTES;   // 131072

__global__ void __launch_bounds__(256, 1) k_gemm(float* __restrict__ out) {
    extern __shared__ char smem[];
    const uint32_t sb = smem_u32(smem);
    const int t = threadIdx.x;
    const int w = t >> 5, l = t & 31;
    const int m0 = blockIdx.y * BM, n0 = blockIdx.x * BN;
    const int wm = (w >> 2) * 64, wn = (w & 3) * 32;   // 2x4 warp grid, warp 64x32

    // loader: thread t -> row r = t>>1 (0..127), half h = t&1 (4 x 16B chunks)
    const int r = t >> 1, h = t & 1;
    const __half* gA = g_xh + (size_t)(m0 + r) * KK + h * 32;
    const __half* gB = g_w2 + (size_t)(n0 + r) * KK + h * 32;
    const uint32_t rowoff = (uint32_t)r * 128u;
    const uint32_t rx = (uint32_t)(r & 7);

    float acc[4][4][4];
#pragma unroll
    for (int i = 0; i < 4; ++i)
#pragma unroll
        for (int j = 0; j < 4; ++j)
#pragma unroll
            for (int k = 0; k < 4; ++k) acc[i][j][k] = 0.f;

    auto load_stage = [&](int it) {
        const uint32_t st = sb + (uint32_t)(it & (STG - 1)) * STAGE_BYTES;
        const uint32_t ab = st + rowoff, bb = ab + ATILE;
        const __half* ga = gA + (size_t)it * KT;
        const __half* gb = gB + (size_t)it * KT;
#pragma unroll
        for (int i = 0; i < 4; ++i) {
            const uint32_t so = (((uint32_t)(4 * h + i) ^ rx) * 16u);
            cpa16(ab + so, ga + i * 8);
            cpa16(bb + so, gb + i * 8);
        }
    };

#pragma unroll
    for (int s = 0; s < STG - 1; ++s) { load_stage(s); CP_COMMIT(); }

    // ldmatrix lane geometry (verified in R3)
    const int arow_i = (l & 7) + ((l >> 3) & 1) * 8, achk_i = (l >> 4);
    const int brow_i = (l & 7) + ((l >> 4) << 3),   bchk_i = (l >> 3) & 1;

    uint32_t af[2][4][4], bf[2][2][4];
    auto load_frags = [&](int ks, int buf, uint32_t st) {
#pragma unroll
        for (int mi = 0; mi < 4; ++mi) {
            const int row = wm + mi * 16 + arow_i, chk = achk_i + ks * 2;
            ldsm4(af[buf][mi], st + (uint32_t)(row * 128 + ((chk ^ (row & 7)) * 16)));
        }
#pragma unroll
        for (int nj = 0; nj < 2; ++nj) {
            const int row = wn + nj * 16 + brow_i, chk = bchk_i + ks * 2;
            ldsm4(bf[buf][nj], st + ATILE + (uint32_t)(row * 128 + ((chk ^ (row & 7)) * 16)));
        }
    };

    for (int it = 0; it < NIT; ++it) {
        CP_WAIT(STG - 2);
        __syncthreads();
        if (it + STG - 1 < NIT) load_stage(it + STG - 1);
        CP_COMMIT();

        const uint32_t st = sb + (uint32_t)(it & (STG - 1)) * STAGE_BYTES;
        load_frags(0, 0, st);
#pragma unroll
        for (int ks = 0; ks < KT / 16; ++ks) {
            if (ks + 1 < KT / 16) load_frags(ks + 1, (ks + 1) & 1, st);
            const int bu = ks & 1;
#pragma unroll
            for (int mi = 0; mi < 4; ++mi)
#pragma unroll
                for (int j = 0; j < 4; ++j)
                    mma16816(acc[mi][j], af[bu][mi],
                             bf[bu][j >> 1][(j & 1) * 2], bf[bu][j >> 1][(j & 1) * 2 + 1]);
        }
    }

#pragma unroll
    for (int mi = 0; mi < 4; ++mi) {
        const int row = m0 + wm + mi * 16 + (l >> 2);
#pragma unroll
        for (int j = 0; j < 4; ++j) {
            const int col = n0 + wn + j * 8 + (l & 3) * 2;
            float2 lo; lo.x = acc[mi][j][0]; lo.y = acc[mi][j][1];
            float2 hi; hi.x = acc[mi][j][2]; hi.y = acc[mi][j][3];
            *reinterpret_cast<float2*>(out + (size_t)row * NO + col) = lo;
            *reinterpret_cast<float2*>(out + (size_t)(row + 8) * NO + col) = hi;
        }
    }
}

extern "C" void kernel_launch(void* const* d_in, const int* in_sizes, int n_in,
                              void* d_out, int out_size) {
    (void)in_sizes; (void)n_in; (void)out_size;
    const float* x  = (const float*)d_in[0];
    const float* Wp = (const float*)d_in[1];
    const float* Wc = (const float*)d_in[2];
    float* out = (float*)d_out;

    k_convert<<<(MB * (KK / 4)) / 256, 256>>>(reinterpret_cast<const float4*>(x));
    k_w2<<<NO, 256>>>(Wp, Wc);
    cudaFuncSetAttribute(k_gemm, cudaFuncAttributeMaxDynamicSharedMemorySize,
                         (int)SMEM_BYTES);
    dim3 grid(NO / BN, MB / BM);
    k_gemm<<<grid, 256, SMEM_BYTES>>>(out);
}

// round 5
// speedup vs baseline: 1.6469x; 1.1882x over previous
#include <cuda_runtime.h>
#include <cuda_fp16.h>
#include <cstdint>
#include <cstddef>

// out = x[1024,65536] @ W2[2048,65536]^T, W2[o,l*32+c]=W_pos[o,l]*W_chan[o,c].
// fp16 operands / fp32 accum, mma.sync.m16n8k16. CTA 128x128x64, 16 warps
// (warp tile 32x32 -> 4 warps/SMSP to cover HMMA/LDS latency), 4-stage cp.async.

static constexpr int MB = 1024, NO = 2048, LL = 2048, CC = 32;
static constexpr int KK = LL * CC;                  // 65536

__device__ __half g_xh[(size_t)MB * KK];
__device__ __half g_w2[(size_t)NO * KK];

__device__ __forceinline__ uint32_t pk(float a, float b) {
    __half2 h = __floats2half2_rn(a, b);
    return *reinterpret_cast<uint32_t*>(&h);
}

__global__ void k_convert(const float4* __restrict__ x4) {
    int i = blockIdx.x * 256 + threadIdx.x;
    float4 v = x4[i];
    uint2 u; u.x = pk(v.x, v.y); u.y = pk(v.z, v.w);
    reinterpret_cast<uint2*>(g_xh)[i] = u;
}

__global__ void k_w2(const float* __restrict__ Wp, const float* __restrict__ Wc) {
    int o = blockIdx.x;
    __shared__ float wc[CC];
    if (threadIdx.x < CC) wc[threadIdx.x] = Wc[o * CC + threadIdx.x];
    __syncthreads();
    for (int l = threadIdx.x; l < LL; l += blockDim.x) {
        float wp = Wp[o * LL + l];
        uint4* dst = reinterpret_cast<uint4*>(g_w2 + (size_t)o * KK + (size_t)l * CC);
#pragma unroll
        for (int q = 0; q < 4; ++q) {
            uint4 u;
            u.x = pk(wp * wc[8*q+0], wp * wc[8*q+1]);
            u.y = pk(wp * wc[8*q+2], wp * wc[8*q+3]);
            u.z = pk(wp * wc[8*q+4], wp * wc[8*q+5]);
            u.w = pk(wp * wc[8*q+6], wp * wc[8*q+7]);
            dst[q] = u;
        }
    }
}

__device__ __forceinline__ uint32_t smem_u32(const void* p) {
    uint32_t a;
    asm("{ .reg .u64 t; cvta.to.shared.u64 t, %1; cvt.u32.u64 %0, t; }" : "=r"(a) : "l"(p));
    return a;
}
__device__ __forceinline__ void cpa16(uint32_t s, const void* g) {
    asm volatile("cp.async.cg.shared.global [%0], [%1], 16;" :: "r"(s), "l"(g) : "memory");
}
#define CP_COMMIT() asm volatile("cp.async.commit_group;" ::: "memory")
#define CP_WAIT(n)  asm volatile("cp.async.wait_group %0;" :: "n"(n) : "memory")

__device__ __forceinline__ void ldsm4(uint32_t* r, uint32_t a) {
    asm volatile("ldmatrix.sync.aligned.m8n8.x4.shared.b16 {%0,%1,%2,%3}, [%4];"
                 : "=r"(r[0]), "=r"(r[1]), "=r"(r[2]), "=r"(r[3]) : "r"(a));
}
__device__ __forceinline__ void mma16816(float* c, const uint32_t* a,
                                         uint32_t b0, uint32_t b1) {
    asm volatile("mma.sync.aligned.m16n8k16.row.col.f32.f16.f16.f32 "
                 "{%0,%1,%2,%3}, {%4,%5,%6,%7}, {%8,%9}, {%0,%1,%2,%3};"
                 : "+f"(c[0]), "+f"(c[1]), "+f"(c[2]), "+f"(c[3])
                 : "r"(a[0]), "r"(a[1]), "r"(a[2]), "r"(a[3]), "r"(b0), "r"(b1));
}

static constexpr int BM = 128, BN = 128, KT = 64;
static constexpr int NIT = KK / KT;                 // 1024
static constexpr int STG = 4;
static constexpr uint32_t ATILE = BM * KT * 2;      // 16384
static constexpr uint32_t STAGE_BYTES = 2 * ATILE;  // 32768
static constexpr uint32_t SMEM_BYTES = STG * STAGE_BYTES;   // 131072

__global__ void __launch_bounds__(512, 1) k_gemm(float* __restrict__ out) {
    extern __shared__ char smem[];
    const uint32_t sb = smem_u32(smem);
    const int t = threadIdx.x;
    const int w = t >> 5, l = t & 31;
    const int m0 = blockIdx.y * BM, n0 = blockIdx.x * BN;
    const int wm = (w >> 2) * 32, wn = (w & 3) * 32;   // 4x4 warp grid, warp 32x32

    // loader: 512 threads; thread -> row r = t>>2, quarter q = t&3 (2 x 16B per tile)
    const int r = t >> 2, q = t & 3;
    const __half* gA = g_xh + (size_t)(m0 + r) * KK + q * 16;
    const __half* gB = g_w2 + (size_t)(n0 + r) * KK + q * 16;
    const uint32_t rowoff = (uint32_t)r * 128u;
    const uint32_t rx = (uint32_t)(r & 7);

    float acc[2][4][4];
#pragma unroll
    for (int i = 0; i < 2; ++i)
#pragma unroll
        for (int j = 0; j < 4; ++j)
#pragma unroll
            for (int k = 0; k < 4; ++k) acc[i][j][k] = 0.f;

    auto load_stage = [&](int it) {
        const uint32_t st = sb + (uint32_t)(it & (STG - 1)) * STAGE_BYTES;
        const uint32_t ab = st + rowoff, bb = ab + ATILE;
        const __half* ga = gA + (size_t)it * KT;
        const __half* gb = gB + (size_t)it * KT;
#pragma unroll
        for (int i = 0; i < 2; ++i) {
            const uint32_t c = (uint32_t)(2 * q + i);
            const uint32_t so = ((c ^ rx) * 16u);
            cpa16(ab + so, ga + i * 8);
            cpa16(bb + so, gb + i * 8);
        }
    };

#pragma unroll
    for (int s = 0; s < STG - 1; ++s) { load_stage(s); CP_COMMIT(); }

    // ldmatrix lane geometry (verified R3/R4)
    const int arow_i = (l & 7) + ((l >> 3) & 1) * 8, achk_i = (l >> 4);
    const int brow_i = (l & 7) + ((l >> 4) << 3),   bchk_i = (l >> 3) & 1;

    uint32_t af[2][2][4], bf[2][2][4];
    auto load_frags = [&](int ks, int buf, uint32_t st) {
#pragma unroll
        for (int mi = 0; mi < 2; ++mi) {
            const int row = wm + mi * 16 + arow_i, chk = achk_i + ks * 2;
            ldsm4(af[buf][mi], st + (uint32_t)(row * 128 + ((chk ^ (row & 7)) * 16)));
        }
#pragma unroll
        for (int nj = 0; nj < 2; ++nj) {
            const int row = wn + nj * 16 + brow_i, chk = bchk_i + ks * 2;
            ldsm4(bf[buf][nj], st + ATILE + (uint32_t)(row * 128 + ((chk ^ (row & 7)) * 16)));
        }
    };

    for (int it = 0; it < NIT; ++it) {
        CP_WAIT(STG - 2);
        __syncthreads();
        if (it + STG - 1 < NIT) load_stage(it + STG - 1);
        CP_COMMIT();

        const uint32_t st = sb + (uint32_t)(it & (STG - 1)) * STAGE_BYTES;
        load_frags(0, 0, st);
#pragma unroll
        for (int ks = 0; ks < KT / 16; ++ks) {
            if (ks + 1 < KT / 16) load_frags(ks + 1, (ks + 1) & 1, st);
            const int bu = ks & 1;
#pragma unroll
            for (int mi = 0; mi < 2; ++mi)
#pragma unroll
                for (int j = 0; j < 4; ++j)
                    mma16816(acc[mi][j], af[bu][mi],
                             bf[bu][j >> 1][(j & 1) * 2], bf[bu][j >> 1][(j & 1) * 2 + 1]);
        }
    }

#pragma unroll
    for (int mi = 0; mi < 2; ++mi) {
        const int row = m0 + wm + mi * 16 + (l >> 2);
#pragma unroll
        for (int j = 0; j < 4; ++j) {
            const int col = n0 + wn + j * 8 + (l & 3) * 2;
            float2 lo; lo.x = acc[mi][j][0]; lo.y = acc[mi][j][1];
            float2 hi; hi.x = acc[mi][j][2]; hi.y = acc[mi][j][3];
            *reinterpret_cast<float2*>(out + (size_t)row * NO + col) = lo;
            *reinterpret_cast<float2*>(out + (size_t)(row + 8) * NO + col) = hi;
        }
    }
}

extern "C" void kernel_launch(void* const* d_in, const int* in_sizes, int n_in,
                              void* d_out, int out_size) {
    (void)in_sizes; (void)n_in; (void)out_size;
    const float* x  = (const float*)d_in[0];
    const float* Wp = (const float*)d_in[1];
    const float* Wc = (const float*)d_in[2];
    float* out = (float*)d_out;

    k_convert<<<(MB * (KK / 4)) / 256, 256>>>(reinterpret_cast<const float4*>(x));
    k_w2<<<NO, 256>>>(Wp, Wc);
    cudaFuncSetAttribute(k_gemm, cudaFuncAttributeMaxDynamicSharedMemorySize,
                         (int)SMEM_BYTES);
    dim3 grid(NO / BN, MB / BM);
    k_gemm<<<grid, 512, SMEM_BYTES>>>(out);
}